// round 7
// baseline (speedup 1.0000x reference)
#include <cuda_runtime.h>
#include <cstdint>

#define B 8192
#define NNODE 64
#define DOBS 16
#define XROW 18
#define XLEN (B * NNODE * XROW)          // 9437184 floats (x region)
#define EPB 630                          // max edge columns per batch
#define ETOT (B * EPB)                   // 5160960 columns
#define KEY_STRIDE 640

__device__ unsigned short g_keys[(size_t)B * KEY_STRIDE];
__device__ int g_cnt[B];
__device__ int g_off[B];
__device__ int g_total;

#define BAR64() asm volatile("bar.sync 1, 64;" ::: "memory")

// ---------------------------------------------------------------------------
// Kernel 1: warp-specialized. Threads 64-127: x-write. Threads 0-63: edges.
// ---------------------------------------------------------------------------
__global__ void __launch_bounds__(128) build_edges_x(const float* __restrict__ obs,
                                                     const float* __restrict__ ego,
                                                     const float* __restrict__ other,
                                                     float* __restrict__ out) {
    int b = blockIdx.x;
    int t = threadIdx.x;

    __shared__ float sy[64];
    __shared__ unsigned long long skey[64];
    __shared__ int sord[64];
    __shared__ unsigned sbits[5][2];
    __shared__ unsigned bitmap[128];       // 4096 bits: key = u*64 + v
    __shared__ int warpsum[2];

    if (t >= 64) {
        // ---------- x-write path: one full row per thread, no barriers ----------
        int j = t - 64;
        const float4* row4 = (const float4*)(obs + (size_t)b * NNODE * DOBS + j * DOBS);
        float4 f0 = row4[0], f1 = row4[1], f2 = row4[2], f3 = row4[3];
        float2* p = (float2*)(out + (size_t)b * NNODE * XROW + j * XROW);
        p[0] = make_float2(f0.x, f0.y); p[1] = make_float2(f0.z, f0.w);
        p[2] = make_float2(f1.x, f1.y); p[3] = make_float2(f1.z, f1.w);
        p[4] = make_float2(f2.x, f2.y); p[5] = make_float2(f2.z, f2.w);
        p[6] = make_float2(f3.x, f3.y); p[7] = make_float2(f3.z, f3.w);
        p[8] = (j == 0) ? make_float2(ego[0], ego[1])
                        : make_float2(other[0], other[1]);
        return;
    }

    // ---------- edge path: threads 0-63 (warps 0,1), named barriers ----------
    int lane = t & 31, w = t >> 5;

    float2 xy = *(const float2*)(obs + (size_t)b * NNODE * DOBS + t * DOBS);
    // x in [0,1): float bits preserve order; tie-break by index
    unsigned long long ki =
        (((unsigned long long)__float_as_uint(xy.x)) << 6) | (unsigned)t;
    skey[t] = ki;
    sy[t] = xy.y;
    bitmap[t] = 0u;
    bitmap[t + 64] = 0u;
    BAR64();

    // stable rank by x: 64 broadcast LDS.64 compares
    int r = 0;
#pragma unroll 16
    for (int j = 0; j < 64; j++) r += (skey[j] < ki);
    sord[r] = t;
    BAR64();

    // thread t = sorted position t
    int node = sord[t];
    float ys = sy[node];
    const float T1 = (float)(1.0 / 3.0);
    const float T2 = (float)(2.0 / 3.0);
    bool f0m = (ys <= T1) && (ys > 0.0f);
    bool f1m = (ys > T1) && (ys <= T2);
    bool f2m = (ys >= T2) && (ys < 1.0f);
    bool mm[5] = { f0m, f1m, f2m, f0m || f1m, f1m || f2m };
#pragma unroll
    for (int m = 0; m < 5; m++) {
        unsigned bal = __ballot_sync(0xffffffffu, mm[m]);
        if (lane == 0) sbits[m][w] = bal;
    }
    BAR64();

    // chain edges into bitmap
#pragma unroll
    for (int m = 0; m < 5; m++) {
        if (mm[m] && t < 63) {
            unsigned long long bits =
                ((unsigned long long)sbits[m][1] << 32) | (unsigned long long)sbits[m][0];
            unsigned long long rest = bits >> (t + 1);
            if (rest) {
                int nk = t + 1 + (__ffsll((long long)rest) - 1);
                int v = sord[nk];
                int k1 = node * 64 + v;
                int k2 = v * 64 + node;
                atomicOr(&bitmap[k1 >> 5], 1u << (k1 & 31));
                atomicOr(&bitmap[k2 >> 5], 1u << (k2 & 31));
            }
        }
    }
    BAR64();

    // compact: thread t owns bitmap words 2t, 2t+1
    uint2 bw = *(const uint2*)&bitmap[2 * t];
    unsigned w0 = bw.x, w1 = bw.y;
    int c = __popc(w0) + __popc(w1);

    int inc = c;
#pragma unroll
    for (int d = 1; d < 32; d <<= 1) {
        int nv = __shfl_up_sync(0xffffffffu, inc, d);
        if (lane >= d) inc += nv;
    }
    if (lane == 31) warpsum[w] = inc;
    BAR64();
    int excl = inc - c + (w ? warpsum[0] : 0);
    if (t == 0) g_cnt[b] = warpsum[0] + warpsum[1];

    unsigned short* kb = g_keys + (size_t)b * KEY_STRIDE;
    int pos = excl;
    int kbase = t * 64;
    while (w0) {
        int bit = __ffs(w0) - 1;
        w0 &= (w0 - 1);
        kb[pos++] = (unsigned short)(kbase + bit);
    }
    kbase += 32;
    while (w1) {
        int bit = __ffs(w1) - 1;
        w1 &= (w1 - 1);
        kb[pos++] = (unsigned short)(kbase + bit);
    }
}

// ---------------------------------------------------------------------------
// Kernel 2: exclusive scan of g_cnt[8192] -> g_off, + g_total
// ---------------------------------------------------------------------------
__global__ void __launch_bounds__(1024) scan_counts() {
    int t = threadIdx.x;
    int lane = t & 31, wid = t >> 5;
    __shared__ int wsum[32];

    int base = t * 8;
    int v[8];
    int s = 0;
#pragma unroll
    for (int i = 0; i < 8; i++) {
        v[i] = s;
        s += g_cnt[base + i];
    }
    int inc = s;
#pragma unroll
    for (int d = 1; d < 32; d <<= 1) {
        int nv = __shfl_up_sync(0xffffffffu, inc, d);
        if (lane >= d) inc += nv;
    }
    if (lane == 31) wsum[wid] = inc;
    __syncthreads();
    if (wid == 0) {
        int wv = wsum[lane];
        int winc = wv;
#pragma unroll
        for (int d = 1; d < 32; d <<= 1) {
            int nv = __shfl_up_sync(0xffffffffu, winc, d);
            if (lane >= d) winc += nv;
        }
        wsum[lane] = winc - wv;   // exclusive warp offsets
    }
    __syncthreads();
    int excl = inc - s + wsum[wid];
#pragma unroll
    for (int i = 0; i < 8; i++) g_off[base + i] = excl + v[i];
    if (t == 1023) g_total = excl + s;
}

// ---------------------------------------------------------------------------
// Kernel 3: scatter valid edges + this block's share of the -1 pad
// ---------------------------------------------------------------------------
__global__ void __launch_bounds__(256) scatter_pad(float* __restrict__ out) {
    int b = blockIdx.x;
    int t = threadIdx.x;
    int cnt = g_cnt[b];
    int off = g_off[b];
    const unsigned short* kb = g_keys + (size_t)b * KEY_STRIDE;
    float* src_out = out + XLEN;
    float* dst_out = out + XLEN + ETOT;
    int nb = b * NNODE;
    for (int i = t; i < cnt; i += 256) {
        int k = kb[i];
        src_out[off + i] = (float)(nb + (k >> 6));
        dst_out[off + i] = (float)(nb + (k & 63));
    }
    // pad share
    int T = g_total;
    int P = ETOT - T;
    int chunk = (P + B - 1) / B;
    int start = T + b * chunk;
    int end = start + chunk;
    if (end > ETOT) end = ETOT;
    for (int i = start + t; i < end; i += 256) {
        src_out[i] = -1.0f;
        dst_out[i] = -1.0f;
    }
}

// ---------------------------------------------------------------------------
extern "C" void kernel_launch(void* const* d_in, const int* in_sizes, int n_in,
                              void* d_out, int out_size) {
    const float* obs = (const float*)d_in[0];
    const float* ego = (const float*)d_in[1];
    const float* other = (const float*)d_in[2];
    float* out = (float*)d_out;

    build_edges_x<<<B, 128>>>(obs, ego, other, out);
    scan_counts<<<1, 1024>>>();
    scatter_pad<<<B, 256>>>(out);
}

// round 8
// speedup vs baseline: 1.3038x; 1.3038x over previous
#include <cuda_runtime.h>
#include <cstdint>

#define B 8192
#define NNODE 64
#define DOBS 16
#define XROW 18
#define XLEN (B * NNODE * XROW)          // 9437184 floats (x region)
#define EPB 630                          // max edge columns per batch
#define ETOT (B * EPB)                   // 5160960 columns
#define KEY_STRIDE 640

#define SCAT_BLOCKS 1024
#define BPB (B / SCAT_BLOCKS)            // 8 batches per scatter block

__device__ unsigned short g_keys[(size_t)B * KEY_STRIDE];
__device__ int g_cnt[B];
__device__ int g_off[B];
__device__ int g_total;

// ---------------------------------------------------------------------------
// Kernel 1: fused x-write + per-batch edge keys. 128 thr/block. (R5 version)
// ---------------------------------------------------------------------------
__global__ void __launch_bounds__(128) build_edges_x(const float* __restrict__ obs,
                                                     const float* __restrict__ ego,
                                                     const float* __restrict__ other,
                                                     float* __restrict__ out) {
    int b = blockIdx.x;
    int t = threadIdx.x;              // 0..127
    int lane = t & 31, w = t >> 5;

    __shared__ float sx[64], sy[64];
    __shared__ unsigned long long skey[64];
    __shared__ int spart[128];
    __shared__ int sord[64];
    __shared__ unsigned sbits[5][2];
    __shared__ unsigned bitmap[128];       // 4096 bits: key = u*64 + v
    __shared__ int warpsum[4];

    const float4* src4 = (const float4*)(obs + (size_t)b * NNODE * DOBS);
    float* xout = out + (size_t)b * NNODE * XROW;

    float4 fa = src4[t];
    float4 fb = src4[t + 128];
    bitmap[t] = 0u;

    // extract x,y columns (row n starts at float4 index n*4)
    if ((t & 3) == 0) { sx[t >> 2] = fa.x; sy[t >> 2] = fa.y; }
    { int i = t + 128; if ((i & 3) == 0) { sx[i >> 2] = fb.x; sy[i >> 2] = fb.y; } }

    // write obs part of x directly: float4 i -> out row n=i>>2, cols 4(i&3)..+3
    {
        int n = t >> 2, q = t & 3;
        float2* p = (float2*)(xout + n * XROW + q * 4);
        p[0] = make_float2(fa.x, fa.y);
        p[1] = make_float2(fa.z, fa.w);
    }
    {
        int i = t + 128;
        int n = i >> 2, q = i & 3;
        float2* p = (float2*)(xout + n * XROW + q * 4);
        p[0] = make_float2(fb.x, fb.y);
        p[1] = make_float2(fb.z, fb.w);
    }
    // init columns 16,17
    if (t < 64) {
        float2 iv = (t == 0) ? make_float2(ego[0], ego[1])
                             : make_float2(other[0], other[1]);
        *(float2*)(xout + t * XROW + DOBS) = iv;
    }
    __syncthreads();   // sx/sy fully written

    // sortable key: x in [0,1) so float bits preserve order; tie-break by index
    if (t < 64) {
        skey[t] = (((unsigned long long)__float_as_uint(sx[t])) << 6) | (unsigned)t;
    }
    __syncthreads();

    // --- stable rank by x: 128 threads, 32 u64 compares each ---
    {
        int node = t & 63;
        int jbase = (t >> 6) * 32;
        unsigned long long ki = skey[node];
        int r = 0;
#pragma unroll
        for (int jj = 0; jj < 32; jj++) {
            r += (skey[jbase + jj] < ki);
        }
        spart[t] = r;
    }
    __syncthreads();
    if (t < 64) sord[spart[t] + spart[t + 64]] = t;
    __syncthreads();

    // --- lane masks + chain edges into bitmap ---
    bool mm[5];
    int node = 0;
    if (t < 64) {
        node = sord[t];               // node at sorted position t
        float ys = sy[node];
        const float T1 = (float)(1.0 / 3.0);
        const float T2 = (float)(2.0 / 3.0);
        bool f0 = (ys <= T1) && (ys > 0.0f);
        bool f1 = (ys > T1) && (ys <= T2);
        bool f2 = (ys >= T2) && (ys < 1.0f);
        mm[0] = f0; mm[1] = f1; mm[2] = f2; mm[3] = f0 || f1; mm[4] = f1 || f2;
#pragma unroll
        for (int m = 0; m < 5; m++) {
            unsigned bal = __ballot_sync(0xffffffffu, mm[m]);
            if (lane == 0) sbits[m][w] = bal;
        }
    }
    __syncthreads();

    if (t < 64) {
#pragma unroll
        for (int m = 0; m < 5; m++) {
            if (mm[m] && t < 63) {
                unsigned long long bits =
                    ((unsigned long long)sbits[m][1] << 32) | (unsigned long long)sbits[m][0];
                unsigned long long rest = bits >> (t + 1);
                if (rest) {
                    int nk = t + 1 + (__ffsll((long long)rest) - 1);
                    int v = sord[nk];
                    int k1 = node * 64 + v;
                    int k2 = v * 64 + node;
                    atomicOr(&bitmap[k1 >> 5], 1u << (k1 & 31));
                    atomicOr(&bitmap[k2 >> 5], 1u << (k2 & 31));
                }
            }
        }
    }
    __syncthreads();

    // --- compact: each of 128 threads owns one 32-bit bitmap word ---
    unsigned wv = bitmap[t];
    int c = __popc(wv);
    int inc = c;
#pragma unroll
    for (int d = 1; d < 32; d <<= 1) {
        int nv = __shfl_up_sync(0xffffffffu, inc, d);
        if (lane >= d) inc += nv;
    }
    if (lane == 31) warpsum[w] = inc;
    __syncthreads();
    int wpre = 0;
#pragma unroll
    for (int j = 0; j < 4; j++) wpre += (j < w) ? warpsum[j] : 0;
    int excl = inc - c + wpre;
    if (t == 0) g_cnt[b] = warpsum[0] + warpsum[1] + warpsum[2] + warpsum[3];

    unsigned short* kb = g_keys + (size_t)b * KEY_STRIDE;
    int pos = excl;
    int kbase = t * 32;
    while (wv) {
        int bit = __ffs(wv) - 1;
        wv &= (wv - 1);
        kb[pos++] = (unsigned short)(kbase + bit);
    }
}

// ---------------------------------------------------------------------------
// Kernel 2: exclusive scan of g_cnt[8192] -> g_off, + g_total
// ---------------------------------------------------------------------------
__global__ void __launch_bounds__(1024) scan_counts() {
    int t = threadIdx.x;
    int lane = t & 31, wid = t >> 5;
    __shared__ int wsum[32];

    int base = t * 8;
    int v[8];
    int s = 0;
#pragma unroll
    for (int i = 0; i < 8; i++) {
        v[i] = s;
        s += g_cnt[base + i];
    }
    int inc = s;
#pragma unroll
    for (int d = 1; d < 32; d <<= 1) {
        int nv = __shfl_up_sync(0xffffffffu, inc, d);
        if (lane >= d) inc += nv;
    }
    if (lane == 31) wsum[wid] = inc;
    __syncthreads();
    if (wid == 0) {
        int wv = wsum[lane];
        int winc = wv;
#pragma unroll
        for (int d = 1; d < 32; d <<= 1) {
            int nv = __shfl_up_sync(0xffffffffu, winc, d);
            if (lane >= d) winc += nv;
        }
        wsum[lane] = winc - wv;   // exclusive warp offsets
    }
    __syncthreads();
    int excl = inc - s + wsum[wid];
#pragma unroll
    for (int i = 0; i < 8; i++) g_off[base + i] = excl + v[i];
    if (t == 1023) g_total = excl + s;
}

// ---------------------------------------------------------------------------
// Kernel 3: scatter. 1024 blocks x 256 threads, 8 batches per block.
// ---------------------------------------------------------------------------
__global__ void __launch_bounds__(256) scatter_pad(float* __restrict__ out) {
    int t = threadIdx.x;
    int b0 = blockIdx.x * BPB;
    float* src_out = out + XLEN;
    float* dst_out = out + XLEN + ETOT;

#pragma unroll
    for (int bb = 0; bb < BPB; bb++) {
        int b = b0 + bb;
        int cnt = g_cnt[b];
        int off = g_off[b];
        const unsigned short* kb = g_keys + (size_t)b * KEY_STRIDE;
        int nb = b * NNODE;
        for (int i = t; i < cnt; i += 256) {
            int k = kb[i];
            src_out[off + i] = (float)(nb + (k >> 6));
            dst_out[off + i] = (float)(nb + (k & 63));
        }
    }

    // pad region [T, ETOT): split evenly across SCAT_BLOCKS as contiguous runs
    int T = g_total;
    int P = ETOT - T;
    int chunk = (P + SCAT_BLOCKS - 1) / SCAT_BLOCKS;
    int start = T + blockIdx.x * chunk;
    int end = start + chunk;
    if (end > ETOT) end = ETOT;
    for (int i = start + t; i < end; i += 256) {
        src_out[i] = -1.0f;
        dst_out[i] = -1.0f;
    }
}

// ---------------------------------------------------------------------------
extern "C" void kernel_launch(void* const* d_in, const int* in_sizes, int n_in,
                              void* d_out, int out_size) {
    const float* obs = (const float*)d_in[0];
    const float* ego = (const float*)d_in[1];
    const float* other = (const float*)d_in[2];
    float* out = (float*)d_out;

    build_edges_x<<<B, 128>>>(obs, ego, other, out);
    scan_counts<<<1, 1024>>>();
    scatter_pad<<<SCAT_BLOCKS, 256>>>(out);
}